// round 1
// baseline (speedup 1.0000x reference)
#include <cuda_runtime.h>

#define BB 8
#define GG 64
#define PP 32768
#define NC 80

// scratch: per-(b,g) packed argmax key:  (iou_bits << 32) | (0xFFFFFFFF - p)
__device__ unsigned long long g_key[BB * GG];

__global__ void init_keys_kernel() {
    int i = blockIdx.x * blockDim.x + threadIdx.x;
    if (i < BB * GG) g_key[i] = 0ULL;
}

// Kernel A: per-gt argmax over P predictions.
// One warp handles 128 consecutive preds (4/lane in registers), loops all gts.
__global__ void __launch_bounds__(256) argmax_kernel(const float* __restrict__ gt,
                                                     const float* __restrict__ pr) {
    int warp = (blockIdx.x * blockDim.x + threadIdx.x) >> 5;
    int lane = threadIdx.x & 31;
    int b = warp >> 8;            // 256 chunks of 128 preds per batch
    int chunk = warp & 255;
    int p0 = chunk * 128 + lane * 4;

    const float4* prv = (const float4*)(pr) + (size_t)b * PP;
    float py1[4], px1[4], py2[4], px2[4], pa[4];
#pragma unroll
    for (int j = 0; j < 4; j++) {
        float4 v = prv[p0 + j];
        float hw = v.z * 0.5f, hh = v.w * 0.5f;
        px1[j] = v.x - hw; px2[j] = v.x + hw;
        py1[j] = v.y - hh; py2[j] = v.y + hh;
        pa[j] = v.z * v.w;
    }

    const float* gtb = gt + b * GG * 6;
    for (int g = 0; g < GG; g++) {
        float gcx = gtb[g * 6 + 0];
        if (gcx == -1.0f) continue;   // invalid gt: key stays 0, gated by conf later
        float gcy = gtb[g * 6 + 1], gw = gtb[g * 6 + 2], gh = gtb[g * 6 + 3];
        float ghw = gw * 0.5f, ghh = gh * 0.5f;
        float gx1 = gcx - ghw, gx2 = gcx + ghw;
        float gy1 = gcy - ghh, gy2 = gcy + ghh;
        float ga = gw * gh;

        float biou = -1.0f; int bp = 0;
#pragma unroll
        for (int j = 0; j < 4; j++) {
            float ih = fmaxf(0.f, fminf(gy2, py2[j]) - fmaxf(gy1, py1[j]));
            float iw = fmaxf(0.f, fminf(gx2, px2[j]) - fmaxf(gx1, px1[j]));
            float inter = iw * ih;
            float iou = inter / (ga + pa[j] - inter + 1e-5f);
            if (iou > biou) { biou = iou; bp = p0 + j; }   // strict > keeps lowest p on tie
        }
        unsigned long long key =
            ((unsigned long long)__float_as_uint(biou) << 32) |
            (unsigned)(0xFFFFFFFFu - (unsigned)bp);
#pragma unroll
        for (int o = 16; o > 0; o >>= 1) {
            unsigned long long other = __shfl_xor_sync(0xFFFFFFFFu, key, o);
            key = key > other ? key : other;
        }
        if (lane == 0) atomicMax(&g_key[b * GG + g], key);
    }
}

// Kernel B: per-(b,p) assignment + regression targets + one-hot class write.
__global__ void __launch_bounds__(256) assign_kernel(const float* __restrict__ gt,
                                                     const float* __restrict__ pr,
                                                     float* __restrict__ out) {
    __shared__ float s_gy1[GG], s_gx1[GG], s_gy2[GG], s_gx2[GG];
    __shared__ float s_ga[GG], s_gcx[GG], s_gcy[GG], s_lgw[GG], s_lgh[GG], s_lab[GG];
    __shared__ int   s_bp[GG];
    __shared__ int   s_cls[256];

    int tid = threadIdx.x;
    int b = blockIdx.y;

    if (tid < GG) {
        const float* gr = gt + (b * GG + tid) * 6;
        float cx = gr[0];
        bool valid = (cx != -1.0f);
        float cy = gr[1], w = gr[2], h = gr[3], lab = gr[4], conf = gr[5];
        if (valid) {
            s_gx1[tid] = cx - w * 0.5f; s_gx2[tid] = cx + w * 0.5f;
            s_gy1[tid] = cy - h * 0.5f; s_gy2[tid] = cy + h * 0.5f;
            s_ga[tid] = w * h; s_gcx[tid] = cx; s_gcy[tid] = cy;
            s_lgw[tid] = logf(w); s_lgh[tid] = logf(h);
        } else {
            // far-away benign box: zero intersection with any pred, finite area
            s_gx1[tid] = 4.f; s_gx2[tid] = 4.f; s_gy1[tid] = 4.f; s_gy2[tid] = 4.f;
            s_ga[tid] = 1.f; s_gcx[tid] = 0.f; s_gcy[tid] = 0.f;
            s_lgw[tid] = 0.f; s_lgh[tid] = 0.f;
        }
        s_lab[tid] = lab;
        int bestp = -1;
        if (valid && conf > 0.f) {
            unsigned long long key = g_key[b * GG + tid];
            bestp = (int)(0xFFFFFFFFu - (unsigned)(key & 0xFFFFFFFFull));
        }
        s_bp[tid] = bestp;
    }
    __syncthreads();

    int p = blockIdx.x * 256 + tid;
    float4 pv = ((const float4*)(pr))[(size_t)b * PP + p];
    float phw = pv.z * 0.5f, phh = pv.w * 0.5f;
    float px1 = pv.x - phw, px2 = pv.x + phw;
    float py1 = pv.y - phh, py2 = pv.y + phh;
    float pa = pv.z * pv.w;

    int g_thresh = -1, g_best = -1;
    bool ignore = false;
    float W = 0.f, Scx = 0.f, Scy = 0.f, Slw = 0.f, Slh = 0.f;

#pragma unroll 4
    for (int g = 0; g < GG; g++) {
        float ih = fmaxf(0.f, fminf(s_gy2[g], py2) - fmaxf(s_gy1[g], py1));
        float iw = fmaxf(0.f, fminf(s_gx2[g], px2) - fmaxf(s_gx1[g], px1));
        float inter = iw * ih;
        float den = s_ga[g] + pa - inter + 1e-5f;   // union + eps > 0
        bool th  = inter >= 0.5f * den;             // iou >= 0.5 (division-free)
        bool ig  = (inter >= 0.4f * den) && !th;    // 0.4 <= iou < 0.5
        bool bst = (p == s_bp[g]);
        float w = (th ? 1.f : 0.f) + (bst ? 1.f : 0.f);
        if (th)  g_thresh = g;
        if (bst) g_best = g;
        ignore = ignore || ig;
        W   += w;
        Scx += w * s_gcx[g];
        Scy += w * s_gcy[g];
        Slw += w * s_lgw[g];
        Slh += w * s_lgh[g];
    }

    int win = (g_best >= 0) ? g_best : g_thresh;
    bool matched = (win >= 0);
    int cid = matched ? (int)s_lab[win] : NC;
    float mask = matched ? 0.f : 1.f;
    if (ignore) mask = -1.f;

    float hat_cx = (Scx - W * pv.x) / pv.z;
    float hat_cy = (Scy - W * pv.y) / pv.w;
    float hat_w  = Slw - W * logf(pv.z);
    float hat_h  = Slh - W * logf(pv.w);

    size_t bp_idx = (size_t)b * PP + p;
    float* out_loc  = out + (size_t)BB * PP * NC;
    float* out_mask = out + (size_t)BB * PP * (NC + 4);
    ((float4*)out_loc)[bp_idx] = make_float4(hat_cx, hat_cy, hat_w, hat_h);
    out_mask[bp_idx] = mask;

    s_cls[tid] = cid;
    __syncthreads();

    // block-cooperative contiguous one-hot write: 256 preds * 80 classes = 5120 float4s
    float4* out_cls = (float4*)(out + ((size_t)b * PP + (size_t)blockIdx.x * 256) * NC);
#pragma unroll
    for (int i = 0; i < 20; i++) {
        int idx = i * 256 + tid;
        int pl = idx / 20;
        int c0 = (idx % 20) * 4;
        int cc = s_cls[pl];
        out_cls[idx] = make_float4(c0 == cc ? 1.f : 0.f,
                                   c0 + 1 == cc ? 1.f : 0.f,
                                   c0 + 2 == cc ? 1.f : 0.f,
                                   c0 + 3 == cc ? 1.f : 0.f);
    }
}

extern "C" void kernel_launch(void* const* d_in, const int* in_sizes, int n_in,
                              void* d_out, int out_size) {
    const float* gt = (const float*)d_in[0];   // [8,64,6]
    const float* pr = (const float*)d_in[1];   // [8,32768,4]
    float* out = (float*)d_out;                // cls[8,32768,80] ++ loc[8,32768,4] ++ mask[8,32768,1]

    init_keys_kernel<<<2, 256>>>();
    argmax_kernel<<<256, 256>>>(gt, pr);       // 2048 warps = 8 batches * 256 chunks
    dim3 gridB(PP / 256, BB);
    assign_kernel<<<gridB, 256>>>(gt, pr, out);
}

// round 2
// speedup vs baseline: 1.1717x; 1.1717x over previous
#include <cuda_runtime.h>

#define BB 8
#define GG 64
#define PP 32768
#define NC 80

// scratch: per-(b,g) packed argmax key:  (iou_bits << 32) | (0xFFFFFFFF - p)
__device__ unsigned long long g_key[BB * GG];

// Kernel A: per-gt argmax over P predictions.
// grid = 256 blocks (8 batches x 32), block = 256 (8 warps).
// Each warp owns 128 consecutive preds (4/lane in regs), loops valid gts,
// reduces via shfl, stages per-warp best in smem, block-reduces, 1 atomic/(blk,gt).
__global__ void __launch_bounds__(256) argmax_kernel(const float* __restrict__ gt,
                                                     const float* __restrict__ pr) {
    __shared__ unsigned long long s_key[8 * GG];
    __shared__ float s_gt[GG * 6];

    int tid = threadIdx.x;
    int b = blockIdx.x >> 5;
    int blk = blockIdx.x & 31;
    int warp = tid >> 5;
    int lane = tid & 31;
    int p0 = blk * 1024 + warp * 128 + lane * 4;

    // zero per-warp keys (512 entries) + stage gt rows for this batch
    s_key[tid] = 0ULL; s_key[tid + 256] = 0ULL;
    const float* gtb = gt + b * GG * 6;
    s_gt[tid] = gtb[tid];
    if (tid < 128) s_gt[tid + 256] = gtb[tid + 256];

    // preds: reference uses pr_boxes[0] for every batch
    const float4* prv = (const float4*)pr;
    float py1[4], px1[4], py2[4], px2[4], pa[4];
#pragma unroll
    for (int j = 0; j < 4; j++) {
        float4 v = prv[p0 + j];
        float hw = v.z * 0.5f, hh = v.w * 0.5f;
        px1[j] = v.x - hw; px2[j] = v.x + hw;
        py1[j] = v.y - hh; py2[j] = v.y + hh;
        pa[j] = v.z * v.w;
    }
    __syncthreads();

    for (int g = 0; g < GG; g++) {
        float gcx = s_gt[g * 6 + 0];
        if (gcx == -1.0f) continue;           // invalid gt: key stays 0
        float gcy = s_gt[g * 6 + 1], gw = s_gt[g * 6 + 2], gh = s_gt[g * 6 + 3];
        float ghw = gw * 0.5f, ghh = gh * 0.5f;
        float gx1 = gcx - ghw, gx2 = gcx + ghw;
        float gy1 = gcy - ghh, gy2 = gcy + ghh;
        float ga = gw * gh;

        float biou = -1.0f; int bp = 0;
#pragma unroll
        for (int j = 0; j < 4; j++) {
            float ih = fmaxf(0.f, fminf(gy2, py2[j]) - fmaxf(gy1, py1[j]));
            float iw = fmaxf(0.f, fminf(gx2, px2[j]) - fmaxf(gx1, px1[j]));
            float inter = iw * ih;
            float iou = inter / (ga + pa[j] - inter + 1e-5f);  // exact div: matches ref ordering
            if (iou > biou) { biou = iou; bp = p0 + j; }       // strict > keeps lowest p
        }
        unsigned long long key =
            ((unsigned long long)__float_as_uint(biou) << 32) |
            (unsigned)(0xFFFFFFFFu - (unsigned)bp);
#pragma unroll
        for (int o = 16; o > 0; o >>= 1) {
            unsigned long long other = __shfl_xor_sync(0xFFFFFFFFu, key, o);
            key = key > other ? key : other;
        }
        if (lane == 0) s_key[warp * GG + g] = key;
    }
    __syncthreads();

    // block reduce: thread g reduces 8 warp partials, single atomic per (block, g)
    if (tid < GG) {
        unsigned long long k = 0ULL;
#pragma unroll
        for (int w = 0; w < 8; w++) {
            unsigned long long v = s_key[w * GG + tid];
            k = v > k ? v : k;
        }
        if (k) atomicMax(&g_key[b * GG + tid], k);
    }
}

// Kernel B: per-(b,p) assignment + regression targets + one-hot class write.
__global__ void __launch_bounds__(256) assign_kernel(const float* __restrict__ gt,
                                                     const float* __restrict__ pr,
                                                     float* __restrict__ out) {
    __shared__ float4 s_box[GG];   // gx1, gx2, gy1, gy2
    __shared__ float4 s_sum[GG];   // gcx, gcy, log(gw), log(gh)
    __shared__ int    s_bp[GG];
    __shared__ float  s_lab[GG];
    __shared__ int    s_cls[256];

    int tid = threadIdx.x;
    int b = blockIdx.y;

    if (tid < GG) {
        const float* gr = gt + (b * GG + tid) * 6;
        float cx = gr[0];
        bool valid = (cx != -1.0f);
        float cy = gr[1], w = gr[2], h = gr[3], lab = gr[4], conf = gr[5];
        if (valid) {
            s_box[tid] = make_float4(cx - w * 0.5f, cx + w * 0.5f,
                                     cy - h * 0.5f, cy + h * 0.5f);
            s_sum[tid] = make_float4(cx, cy, logf(w), logf(h));
        } else {
            // degenerate far box: zero area, zero intersection with all preds
            s_box[tid] = make_float4(4.f, 4.f, 4.f, 4.f);
            s_sum[tid] = make_float4(0.f, 0.f, 0.f, 0.f);
        }
        s_lab[tid] = lab;
        int bestp = -1;
        if (valid && conf > 0.f) {
            unsigned long long key = g_key[b * GG + tid];
            bestp = (int)(0xFFFFFFFFu - (unsigned)(key & 0xFFFFFFFFull));
        }
        s_bp[tid] = bestp;
    }
    __syncthreads();

    int p = blockIdx.x * 256 + tid;
    float4 pv = ((const float4*)pr)[p];    // pr_boxes[0] per reference
    float phw = pv.z * 0.5f, phh = pv.w * 0.5f;
    float px1 = pv.x - phw, px2 = pv.x + phw;
    float py1 = pv.y - phh, py2 = pv.y + phh;
    float pa = pv.z * pv.w;

    int g_thresh = -1, g_best = -1;
    bool ignore = false;
    float W = 0.f, Scx = 0.f, Scy = 0.f, Slw = 0.f, Slh = 0.f;

#pragma unroll 4
    for (int g = 0; g < GG; g++) {
        float4 bx = s_box[g];              // one broadcast LDS.128
        int bp = s_bp[g];                  // one broadcast LDS.32
        float iw = fmaxf(0.f, fminf(bx.y, px2) - fmaxf(bx.x, px1));
        float ih = fmaxf(0.f, fminf(bx.w, py2) - fmaxf(bx.z, py1));
        float inter = iw * ih;
        float ga = (bx.y - bx.x) * (bx.w - bx.z);
        float den = ga + pa - inter + 1e-5f;       // union + eps > 0
        bool th  = inter >= 0.5f * den;            // iou >= 0.5, division-free
        bool bst = (p == bp);
        ignore = ignore || ((inter >= 0.4f * den) && !th);
        if (th || bst) {                            // rare: << 1% of warp-iterations
            float4 m = s_sum[g];
            float w = (th ? 1.f : 0.f) + (bst ? 1.f : 0.f);
            if (th)  g_thresh = g;
            if (bst) g_best = g;
            W   += w;
            Scx += w * m.x;
            Scy += w * m.y;
            Slw += w * m.z;
            Slh += w * m.w;
        }
    }

    int win = (g_best >= 0) ? g_best : g_thresh;
    bool matched = (win >= 0);
    int cid = matched ? (int)s_lab[win] : NC;
    float mask = matched ? 0.f : 1.f;
    if (ignore) mask = -1.f;

    float4 loc;
    if (W > 0.f) {                                  // rare: logs/divs only when needed
        loc = make_float4((Scx - W * pv.x) / pv.z,
                          (Scy - W * pv.y) / pv.w,
                          Slw - W * logf(pv.z),
                          Slh - W * logf(pv.w));
    } else {
        loc = make_float4(0.f, 0.f, 0.f, 0.f);      // exact: sums are 0 when W==0
    }

    size_t bp_idx = (size_t)b * PP + p;
    float* out_loc  = out + (size_t)BB * PP * NC;
    float* out_mask = out + (size_t)BB * PP * (NC + 4);
    ((float4*)out_loc)[bp_idx] = loc;
    out_mask[bp_idx] = mask;

    s_cls[tid] = cid;
    __syncthreads();

    // block-cooperative contiguous one-hot write: 256 preds * 80 classes = 5120 float4s
    float4* out_cls = (float4*)(out + ((size_t)b * PP + (size_t)blockIdx.x * 256) * NC);
#pragma unroll
    for (int i = 0; i < 20; i++) {
        int idx = i * 256 + tid;
        int pl = idx / 20;
        int c0 = (idx % 20) * 4;
        int cc = s_cls[pl];
        out_cls[idx] = make_float4(c0 == cc ? 1.f : 0.f,
                                   c0 + 1 == cc ? 1.f : 0.f,
                                   c0 + 2 == cc ? 1.f : 0.f,
                                   c0 + 3 == cc ? 1.f : 0.f);
    }
}

extern "C" void kernel_launch(void* const* d_in, const int* in_sizes, int n_in,
                              void* d_out, int out_size) {
    const float* gt = (const float*)d_in[0];   // [8,64,6]
    const float* pr = (const float*)d_in[1];   // [8,32768,4]
    float* out = (float*)d_out;                // cls[8,32768,80] ++ loc[8,32768,4] ++ mask[8,32768,1]

    void* keys_addr = nullptr;
    cudaGetSymbolAddress(&keys_addr, g_key);
    cudaMemsetAsync(keys_addr, 0, sizeof(unsigned long long) * BB * GG);

    argmax_kernel<<<256, 256>>>(gt, pr);
    dim3 gridB(PP / 256, BB);
    assign_kernel<<<gridB, 256>>>(gt, pr, out);
}

// round 3
// speedup vs baseline: 1.4771x; 1.2607x over previous
#include <cuda_runtime.h>

#define BB 8
#define GG 64
#define PP 32768
#define NC 80
#define ABLK 32   // argmax blocks per batch

// per-(batch, block) partial argmax keys: (iou_bits << 32) | (0xFFFFFFFF - p)
// fully overwritten by every argmax_kernel run -> no init needed, graph-safe.
__device__ unsigned long long g_partial[BB * ABLK * GG];

// Kernel A: per-gt argmax over P preds. grid = BB*ABLK blocks, 256 threads.
// Warp owns 128 preds (4/lane, j*32+lane for coalescing). Running-max filter
// makes exact divisions rare while preserving reference rounded-quotient order.
__global__ void __launch_bounds__(256) argmax_kernel(const float* __restrict__ gt,
                                                     const float* __restrict__ pr) {
    __shared__ unsigned long long s_key[8 * GG];
    __shared__ float s_gt[GG * 6];

    int tid = threadIdx.x;
    int b = blockIdx.x >> 5;
    int blk = blockIdx.x & (ABLK - 1);
    int warp = tid >> 5, lane = tid & 31;
    int pbase = blk * 1024 + warp * 128;

    s_key[tid] = 0ULL; s_key[tid + 256] = 0ULL;
    const float* gtb = gt + b * GG * 6;
    s_gt[tid] = gtb[tid];
    if (tid < 128) s_gt[tid + 256] = gtb[tid + 256];

    const float4* prv = (const float4*)pr;   // pr_boxes[0] per reference
    float px1[4], px2[4], py1[4], py2[4], pa[4];
#pragma unroll
    for (int j = 0; j < 4; j++) {
        float4 v = prv[pbase + j * 32 + lane];
        px1[j] = v.x - v.z * 0.5f; px2[j] = v.x + v.z * 0.5f;
        py1[j] = v.y - v.w * 0.5f; py2[j] = v.y + v.w * 0.5f;
        pa[j] = v.z * v.w;
    }
    __syncthreads();

    for (int g = 0; g < GG; g++) {
        float gcx = s_gt[g * 6 + 0];
        if (gcx == -1.0f) continue;                 // invalid gt: key stays 0
        float gcy = s_gt[g * 6 + 1], gw = s_gt[g * 6 + 2], gh = s_gt[g * 6 + 3];
        float gx1 = gcx - gw * 0.5f, gx2 = gcx + gw * 0.5f;
        float gy1 = gcy - gh * 0.5f, gy2 = gcy + gh * 0.5f;
        float ga = gw * gh;

        float bq = 0.0f;
        int bp = pbase + lane;                      // lane's earliest pred (j=0)
#pragma unroll
        for (int j = 0; j < 4; j++) {
            float iw = fmaxf(0.f, fminf(gx2, px2[j]) - fmaxf(gx1, px1[j]));
            float ih = fmaxf(0.f, fminf(gy2, py2[j]) - fmaxf(gy1, py1[j]));
            float inter = iw * ih;
            float den = (ga + pa[j]) - inter + 1e-5f;   // exact ref expression
            // conservative filter: margin 1e-6 >> div rounding (3e-8), so any
            // candidate whose ROUNDED quotient could be > bq reaches the div.
            float t = bq * den * 0.999999f;
            if (inter > t) {
                float q = inter / den;              // exact IEEE div = ref rounding
                if (q > bq) { bq = q; bp = pbase + j * 32 + lane; }
            }
        }
        unsigned long long key =
            ((unsigned long long)__float_as_uint(bq) << 32) |
            (unsigned)(0xFFFFFFFFu - (unsigned)bp);
#pragma unroll
        for (int o = 16; o > 0; o >>= 1) {
            unsigned long long other = __shfl_xor_sync(0xFFFFFFFFu, key, o);
            key = key > other ? key : other;
        }
        if (lane == 0) s_key[warp * GG + g] = key;
    }
    __syncthreads();

    if (tid < GG) {
        unsigned long long k = 0ULL;
#pragma unroll
        for (int w = 0; w < 8; w++) {
            unsigned long long v = s_key[w * GG + tid];
            k = v > k ? v : k;
        }
        g_partial[(b * ABLK + blk) * GG + tid] = k;   // plain store, no atomic
    }
}

// Kernel B: 2 preds/thread; zero-fill + scatter one-hot; grid (PP/512, BB).
__global__ void __launch_bounds__(256) assign_kernel(const float* __restrict__ gt,
                                                     const float* __restrict__ pr,
                                                     float* __restrict__ out) {
    __shared__ float4 s_box[GG];   // gx1, gx2, gy1, gy2
    __shared__ float4 s_sum[GG];   // gcx, gcy, log(gw), log(gh)
    __shared__ float  s_ga[GG];
    __shared__ float  s_lab[GG];
    __shared__ int    s_bp[GG];

    int tid = threadIdx.x;
    int b = blockIdx.y;

    if (tid < GG) {
        const float* gr = gt + (b * GG + tid) * 6;
        float cx = gr[0];
        bool valid = (cx != -1.0f);
        float cy = gr[1], w = gr[2], h = gr[3];
        s_lab[tid] = gr[4];
        float conf = gr[5];
        if (valid) {
            s_box[tid] = make_float4(cx - w * 0.5f, cx + w * 0.5f,
                                     cy - h * 0.5f, cy + h * 0.5f);
            s_sum[tid] = make_float4(cx, cy, logf(w), logf(h));
            s_ga[tid] = w * h;
        } else {
            s_box[tid] = make_float4(4.f, 4.f, 4.f, 4.f);  // zero-area far box
            s_sum[tid] = make_float4(0.f, 0.f, 0.f, 0.f);
            s_ga[tid] = 0.f;
        }
        unsigned long long k = 0ULL;
#pragma unroll
        for (int i = 0; i < ABLK; i++) {
            unsigned long long v = g_partial[(b * ABLK + i) * GG + tid];
            k = v > k ? v : k;
        }
        s_bp[tid] = (valid && conf > 0.f)
                    ? (int)(0xFFFFFFFFu - (unsigned)(k & 0xFFFFFFFFull)) : -1;
    }

    // contiguous zero-fill of this block's 512-pred class region (84MB stream)
    float4* zc = (float4*)(out + ((size_t)b * PP + (size_t)blockIdx.x * 512) * NC);
    float4 z4 = make_float4(0.f, 0.f, 0.f, 0.f);
#pragma unroll
    for (int i = 0; i < 40; i++) zc[i * 256 + tid] = z4;
    __syncthreads();   // orders zero-fill before the 1.0 scatter below

    int pidx[2];
    pidx[0] = blockIdx.x * 512 + tid;
    pidx[1] = pidx[0] + 256;

    float px1[2], px2[2], py1[2], py2[2], pa[2];
    float4 pv[2];
    float W[2], Scx[2], Scy[2], Slw[2], Slh[2];
    int gth[2], gbe[2];
    bool ign[2];
#pragma unroll
    for (int k = 0; k < 2; k++) {
        pv[k] = ((const float4*)pr)[pidx[k]];
        px1[k] = pv[k].x - pv[k].z * 0.5f; px2[k] = pv[k].x + pv[k].z * 0.5f;
        py1[k] = pv[k].y - pv[k].w * 0.5f; py2[k] = pv[k].y + pv[k].w * 0.5f;
        pa[k] = pv[k].z * pv[k].w;
        W[k] = Scx[k] = Scy[k] = Slw[k] = Slh[k] = 0.f;
        gth[k] = gbe[k] = -1;
        ign[k] = false;
    }

#pragma unroll 8
    for (int g = 0; g < GG; g++) {
        float4 bx = s_box[g];
        float ga = s_ga[g];
        int bp = s_bp[g];
#pragma unroll
        for (int k = 0; k < 2; k++) {
            float iw = fmaxf(0.f, fminf(bx.y, px2[k]) - fmaxf(bx.x, px1[k]));
            float ih = fmaxf(0.f, fminf(bx.w, py2[k]) - fmaxf(bx.z, py1[k]));
            float inter = iw * ih;
            float den = (ga + pa[k]) - inter + 1e-5f;
            bool th  = inter >= 0.5f * den;
            bool bst = (pidx[k] == bp);
            ign[k] = ign[k] || ((inter >= 0.4f * den) && !th);
            if (th || bst) {                       // rare
                float4 m = s_sum[g];
                float w = (th ? 1.f : 0.f) + (bst ? 1.f : 0.f);
                if (th)  gth[k] = g;
                if (bst) gbe[k] = g;
                W[k]   += w;
                Scx[k] += w * m.x;
                Scy[k] += w * m.y;
                Slw[k] += w * m.z;
                Slh[k] += w * m.w;
            }
        }
    }

    float* out_loc  = out + (size_t)BB * PP * NC;
    float* out_mask = out + (size_t)BB * PP * (NC + 4);
    float* cls_base = out + (size_t)b * PP * NC;

#pragma unroll
    for (int k = 0; k < 2; k++) {
        int win = (gbe[k] >= 0) ? gbe[k] : gth[k];
        bool matched = (win >= 0);
        float mask = matched ? 0.f : 1.f;
        if (ign[k]) mask = -1.f;

        float4 loc;
        if (W[k] > 0.f) {
            loc = make_float4((Scx[k] - W[k] * pv[k].x) / pv[k].z,
                              (Scy[k] - W[k] * pv[k].y) / pv[k].w,
                              Slw[k] - W[k] * logf(pv[k].z),
                              Slh[k] - W[k] * logf(pv[k].w));
        } else {
            loc = make_float4(0.f, 0.f, 0.f, 0.f);  // exact when W==0
        }

        size_t bp_idx = (size_t)b * PP + pidx[k];
        ((float4*)out_loc)[bp_idx] = loc;
        out_mask[bp_idx] = mask;

        if (matched) {                               // sparse one-hot scatter
            int cid = (int)s_lab[win];
            cls_base[(size_t)pidx[k] * NC + cid] = 1.0f;
        }
    }
}

extern "C" void kernel_launch(void* const* d_in, const int* in_sizes, int n_in,
                              void* d_out, int out_size) {
    const float* gt = (const float*)d_in[0];   // [8,64,6]
    const float* pr = (const float*)d_in[1];   // [8,32768,4]
    float* out = (float*)d_out;                // cls ++ loc ++ mask

    argmax_kernel<<<BB * ABLK, 256>>>(gt, pr);
    dim3 gridB(PP / 512, BB);
    assign_kernel<<<gridB, 256>>>(gt, pr, out);
}

// round 4
// speedup vs baseline: 1.6980x; 1.1495x over previous
#include <cuda_runtime.h>

#define BB 8
#define GG 64
#define PP 32768
#define NC 80
#define ABLK 32   // argmax blocks per batch

// per-(batch, block) partial argmax keys: (iou_bits << 32) | (0xFFFFFFFF - p)
// fully overwritten every run -> no init needed, graph-safe.
__device__ unsigned long long g_partial[BB * ABLK * GG];

// Kernel A: per-gt argmax over P preds + zero-fill of the 84MB cls region.
// grid = BB*ABLK = 256 blocks, 256 threads.
// Thread = (gt g = tid&63, replica r = tid>>6). Block stages 1024 pred corners
// in smem; each thread scans its replica's 256 preds (warp-uniform address =>
// broadcast LDS). Running-max filter makes exact divisions vanishingly rare
// while preserving the reference rounded-quotient argmax order (margin 1e-6
// >> div rounding error). No shuffles anywhere.
__global__ void __launch_bounds__(256) argmax_zero_kernel(const float* __restrict__ gt,
                                                          const float* __restrict__ pr,
                                                          float* __restrict__ out) {
    __shared__ float4 s_pc[1024];   // px1, px2, py1, py2
    __shared__ float  s_pa[1024];
    __shared__ unsigned long long s_key[256];   // [replica][gt]

    int tid = threadIdx.x;
    int b = blockIdx.x >> 5;
    int blk = blockIdx.x & (ABLK - 1);
    int pbase = blk * 1024;

    const float4* prv = (const float4*)pr;   // pr_boxes[0] per reference
#pragma unroll
    for (int j = 0; j < 4; j++) {
        int p = j * 256 + tid;
        float4 v = prv[pbase + p];
        s_pc[p] = make_float4(v.x - v.z * 0.5f, v.x + v.z * 0.5f,
                              v.y - v.w * 0.5f, v.y + v.w * 0.5f);
        s_pa[p] = v.z * v.w;
    }

    // zero-fill this block's slice of the cls output (fire-and-forget stores
    // drain under the compute below). 256 blocks * 20480 float4 = whole region.
    {
        float4* zc = (float4*)out + (size_t)blockIdx.x * 20480;
        float4 z = make_float4(0.f, 0.f, 0.f, 0.f);
#pragma unroll
        for (int i = 0; i < 80; i++) zc[i * 256 + tid] = z;
    }

    int g = tid & 63, r = tid >> 6;
    const float* gr = gt + (b * GG + g) * 6;
    float cx = gr[0], cy = gr[1], gw = gr[2], gh = gr[3];
    bool valid = (cx != -1.0f);
    float gx1 = cx - gw * 0.5f, gx2 = cx + gw * 0.5f;
    float gy1 = cy - gh * 0.5f, gy2 = cy + gh * 0.5f;
    float ga = gw * gh;
    __syncthreads();

    int base = r * 256;
    float bq = 0.f;
    int bp = pbase + base;          // earliest pred in range (argmax of all-zero row)
#pragma unroll 4
    for (int i = 0; i < 256; i++) {
        float4 c = s_pc[base + i];              // broadcast LDS.128
        float pa = s_pa[base + i];              // broadcast LDS.32
        float iw = fmaxf(0.f, fminf(gx2, c.y) - fmaxf(gx1, c.x));
        float ih = fmaxf(0.f, fminf(gy2, c.w) - fmaxf(gy1, c.z));
        float inter = iw * ih;
        float den = (ga + pa) - inter + 1e-5f;
        if (inter > bq * den * 0.999999f) {     // conservative reject filter
            float q = inter / den;              // rare: exact compare path
            if (q > bq) { bq = q; bp = pbase + base + i; }  // strict >: lowest p on tie
        }
    }
    s_key[r * GG + g] = valid
        ? (((unsigned long long)__float_as_uint(bq) << 32) |
           (unsigned)(0xFFFFFFFFu - (unsigned)bp))
        : 0ULL;
    __syncthreads();

    if (tid < GG) {
        unsigned long long k = 0ULL;
#pragma unroll
        for (int rr = 0; rr < 4; rr++) {
            unsigned long long v = s_key[rr * GG + tid];
            k = v > k ? v : k;
        }
        g_partial[(b * ABLK + blk) * GG + tid] = k;
    }
}

// Kernel B: per-(b,p) assignment. loc + mask writes + sparse one-hot scatter
// (cls region already zeroed by kernel A). Valid gts compacted (order-
// preserving, so max-index winner semantics are unchanged).
__global__ void __launch_bounds__(256) assign_kernel(const float* __restrict__ gt,
                                                     const float* __restrict__ pr,
                                                     float* __restrict__ out) {
    __shared__ float4 s_box[GG];   // gx1, gx2, gy1, gy2
    __shared__ float4 s_sum[GG];   // gcx, gcy, log(gw), log(gh)
    __shared__ int    s_bp[GG];
    __shared__ float  s_lab[GG];
    __shared__ int    s_cnt[2];
    __shared__ int    s_ng;

    int tid = threadIdx.x;
    int b = blockIdx.y;

    float cx, cy, w, h, lab, conf;
    bool valid = false;
    int off = 0;
    if (tid < GG) {
        const float* gr = gt + (b * GG + tid) * 6;
        cx = gr[0]; cy = gr[1]; w = gr[2]; h = gr[3]; lab = gr[4]; conf = gr[5];
        valid = (cx != -1.0f);
        unsigned m = __ballot_sync(0xFFFFFFFFu, valid);
        off = __popc(m & ((1u << (tid & 31)) - 1));
        if ((tid & 31) == 0) s_cnt[tid >> 5] = __popc(m);
    }
    __syncthreads();
    if (tid < GG) {
        if (tid == 0) s_ng = s_cnt[0] + s_cnt[1];
        if (valid) {
            int d = ((tid < 32) ? 0 : s_cnt[0]) + off;
            s_box[d] = make_float4(cx - w * 0.5f, cx + w * 0.5f,
                                   cy - h * 0.5f, cy + h * 0.5f);
            s_sum[d] = make_float4(cx, cy, logf(w), logf(h));
            s_lab[d] = lab;
            unsigned long long k = 0ULL;
#pragma unroll
            for (int i = 0; i < ABLK; i++) {
                unsigned long long v = g_partial[(b * ABLK + i) * GG + tid];
                k = v > k ? v : k;
            }
            s_bp[d] = (conf > 0.f)
                      ? (int)(0xFFFFFFFFu - (unsigned)(k & 0xFFFFFFFFull)) : -1;
        }
    }
    __syncthreads();
    int ng = s_ng;

    int p = blockIdx.x * 256 + tid;
    float4 pv = ((const float4*)pr)[p];
    float px1 = pv.x - pv.z * 0.5f, px2 = pv.x + pv.z * 0.5f;
    float py1 = pv.y - pv.w * 0.5f, py2 = pv.y + pv.w * 0.5f;
    float pa = pv.z * pv.w;

    int gth = -1, gbe = -1;
    bool ign = false;
    float W = 0.f, Scx = 0.f, Scy = 0.f, Slw = 0.f, Slh = 0.f;

#pragma unroll 4
    for (int g = 0; g < ng; g++) {
        float4 bx = s_box[g];
        int bp = s_bp[g];
        float iw = fmaxf(0.f, fminf(bx.y, px2) - fmaxf(bx.x, px1));
        float ih = fmaxf(0.f, fminf(bx.w, py2) - fmaxf(bx.z, py1));
        float inter = iw * ih;
        float ga = (bx.y - bx.x) * (bx.w - bx.z);
        float den = (ga + pa) - inter + 1e-5f;
        bool th  = inter >= 0.5f * den;            // iou >= 0.5, division-free
        bool bst = (p == bp);
        ign = ign || ((inter >= 0.4f * den) && !th);
        if (th || bst) {                            // rare
            float4 m = s_sum[g];
            float wgt = (th ? 1.f : 0.f) + (bst ? 1.f : 0.f);
            if (th)  gth = g;
            if (bst) gbe = g;
            W   += wgt;
            Scx += wgt * m.x;
            Scy += wgt * m.y;
            Slw += wgt * m.z;
            Slh += wgt * m.w;
        }
    }

    int win = (gbe >= 0) ? gbe : gth;
    bool matched = (win >= 0);
    float mask = matched ? 0.f : 1.f;
    if (ign) mask = -1.f;

    float4 loc;
    if (W > 0.f) {
        loc = make_float4((Scx - W * pv.x) / pv.z,
                          (Scy - W * pv.y) / pv.w,
                          Slw - W * logf(pv.z),
                          Slh - W * logf(pv.w));
    } else {
        loc = make_float4(0.f, 0.f, 0.f, 0.f);      // exact when W==0
    }

    size_t bp_idx = (size_t)b * PP + p;
    float* out_loc  = out + (size_t)BB * PP * NC;
    float* out_mask = out + (size_t)BB * PP * (NC + 4);
    ((float4*)out_loc)[bp_idx] = loc;
    out_mask[bp_idx] = mask;

    if (matched) {                                  // sparse one-hot scatter
        int cid = (int)s_lab[win];
        out[((size_t)b * PP + p) * NC + cid] = 1.0f;
    }
}

extern "C" void kernel_launch(void* const* d_in, const int* in_sizes, int n_in,
                              void* d_out, int out_size) {
    const float* gt = (const float*)d_in[0];   // [8,64,6]
    const float* pr = (const float*)d_in[1];   // [8,32768,4]
    float* out = (float*)d_out;                // cls ++ loc ++ mask

    argmax_zero_kernel<<<BB * ABLK, 256>>>(gt, pr, out);
    dim3 gridB(PP / 256, BB);
    assign_kernel<<<gridB, 256>>>(gt, pr, out);
}